// round 16
// baseline (speedup 1.0000x reference)
#include <cuda_runtime.h>

// AREMA: attack/release envelope follower.
// y_t = alpha*x_t + (1-alpha)*y_{t-1}, alpha = a if (x_t - y_{t-1} > 0) else r.
// Since a > r > 0:  y_t = max( fma(a, x-y, y), fma(r, x-y, y) ).
//
// Champion config (3x reproduced at 92.6-93.0us wall, traffic at the 536 MB
// floor, BW at the measured ~6.0 TB/s r/w ceiling). R16 probe: store policy
// __stcs (evict-first; L2 accumulates dirty lines, drains in eviction bursts)
// -> __stwt (write-through; writes drain at issue cadence). Stores are
// full-line (256B/warp/step), so no partial-sector cost. Only the DRAM-level
// r/w interleave changes; traffic and math are bit-identical.

#define BB 8
#define TT 16384
#define FF2 256             // feature columns in float2 units (512 floats)
#define CHUNKS 32
#define LCH (TT / CHUNKS)   // 512 outputs per chunk
#define WARM 96             // warm-up steps (6 phases of UNR=16)
#define UNR 16

#define LOAD(buf)                                                   \
    _Pragma("unroll")                                               \
    for (int u = 0; u < UNR; ++u) buf[u] = xp[u * FF2];             \
    xp += UNR * FF2;

#define STEP(v)                                                     \
    {                                                               \
        float d0 = (v).x - y0;                                      \
        float d1 = (v).y - y1;                                      \
        y0 = fmaxf(fmaf(A, d0, y0), fmaf(R, d0, y0));               \
        y1 = fmaxf(fmaf(A, d1, y1), fmaf(R, d1, y1));               \
    }

#define COMP(buf)                                                   \
    _Pragma("unroll")                                               \
    for (int u = 0; u < UNR; ++u) STEP(buf[u])

#define COMPST(buf)                                                 \
    _Pragma("unroll")                                               \
    for (int u = 0; u < UNR; ++u) {                                 \
        STEP(buf[u])                                                \
        float2 o; o.x = y0; o.y = y1;                               \
        __stwt(yp + u * FF2, o);                                    \
    }                                                               \
    yp += UNR * FF2;

__global__ __launch_bounds__(128)
void arema_kernel(const float2* __restrict__ x, float2* __restrict__ y) {
    const float A = 0.18126924692201818f;   // 1 - exp(-0.001/0.005)
    const float R = 0.019801326693244747f;  // 1 - exp(-0.001/0.05)

    const int f2 = blockIdx.x * 128 + threadIdx.x;  // float2 lane (coalesced)
    const int b  = blockIdx.y;                      // batch
    const int c  = blockIdx.z;                      // chunk along T

    const int t0    = c * LCH;
    const int nwarm = (c == 0) ? 0 : WARM;          // first chunk: exact

    const float2* xp = x + (b * TT + t0 - nwarm) * FF2 + f2;
    float2*       yp = y + (b * TT + t0) * FF2 + f2;

    float2 bufA[UNR], bufB[UNR];
    float y0 = 0.0f, y1 = 0.0f;

    // ---- prologue: prefetch batch 0 ----
    LOAD(bufA)

    // ---- warm-up (read-only), double-buffered: 6 phases = 3 pairs ----
    const int warmPairs = nwarm / (2 * UNR);        // 3 or 0
    for (int i = 0; i < warmPairs; ++i) {
        LOAD(bufB)
        COMP(bufA)
        LOAD(bufA)
        COMP(bufB)
    }

    // ---- main (compute + streaming stores), double-buffered ----
    const int mainPairs = LCH / (2 * UNR) - 1;      // 15
    for (int i = 0; i < mainPairs; ++i) {
        LOAD(bufB)
        COMPST(bufA)
        LOAD(bufA)
        COMPST(bufB)
    }

    // ---- epilogue: last two batches (no prefetch past end) ----
    LOAD(bufB)
    COMPST(bufA)
    COMPST(bufB)
}

extern "C" void kernel_launch(void* const* d_in, const int* in_sizes, int n_in,
                              void* d_out, int out_size) {
    const float2* x = (const float2*)d_in[0];
    float2*       y = (float2*)d_out;
    dim3 grid(FF2 / 128, BB, CHUNKS);  // (2, 8, 32) = 512 blocks x 128 threads
    arema_kernel<<<grid, 128>>>(x, y);
}